// round 8
// baseline (speedup 1.0000x reference)
#include <cuda_runtime.h>

#define NNODES 50000
#define NB 2
#define FDIM 128
#define EDGES_MAX 800000
#define NODES_PB 32
#define NBLOCKS ((NNODES + NODES_PB - 1) / NODES_PB)   // 1563
#define SCAN_BLOCKS ((NNODES + 255) / 256)             // 196

// Scratch: __device__ globals only (zero-initialized at module load; the
// scan pipeline self-clears g_deg each call so graph replays are identical)
__device__ int g_deg[NNODES];
__device__ int g_rowstart[NNODES + 1];
__device__ int g_cursor[NNODES];
__device__ int g_exloc[NNODES];        // block-local exclusive scan temp
__device__ int g_bsum[SCAN_BLOCKS];
__device__ int g_csr[EDGES_MAX];

// ---------------------------------------------------------------------------
// edges int32 [E,2]; int4 = 2 edges per thread
__global__ void k_hist(const int4* __restrict__ edges2, int Epairs) {
    int i = blockIdx.x * blockDim.x + threadIdx.x;
    if (i < Epairs) {
        int4 e2 = edges2[i];
        atomicAdd(&g_deg[e2.y], 1);
        atomicAdd(&g_deg[e2.w], 1);
    }
}

// ---- hierarchical coalesced scan ----
__global__ void __launch_bounds__(256)
k_scan_local() {
    __shared__ int wsum[8];
    const int tid = threadIdx.x;
    const int i = blockIdx.x * 256 + tid;
    const int lane = tid & 31;
    const int wrp = tid >> 5;

    int val = (i < NNODES) ? g_deg[i] : 0;

    int incl = val;
    #pragma unroll
    for (int off = 1; off < 32; off <<= 1) {
        int v = __shfl_up_sync(0xffffffffu, incl, off);
        if (lane >= off) incl += v;
    }
    if (lane == 31) wsum[wrp] = incl;
    __syncthreads();
    if (wrp == 0) {
        int s = (lane < 8) ? wsum[lane] : 0;
        #pragma unroll
        for (int off = 1; off < 8; off <<= 1) {
            int v = __shfl_up_sync(0xffffffffu, s, off);
            if (lane >= off) s += v;
        }
        if (lane < 8) wsum[lane] = s;
    }
    __syncthreads();

    const int warpOff = (wrp == 0) ? 0 : wsum[wrp - 1];
    const int ex = warpOff + incl - val;
    if (i < NNODES) g_exloc[i] = ex;
    if (tid == 255) g_bsum[blockIdx.x] = warpOff + incl;
}

__global__ void __launch_bounds__(256)
k_scan_block() {
    __shared__ int wsum[8];
    const int tid = threadIdx.x;
    const int lane = tid & 31;
    const int wrp = tid >> 5;

    int val = (tid < SCAN_BLOCKS) ? g_bsum[tid] : 0;
    int incl = val;
    #pragma unroll
    for (int off = 1; off < 32; off <<= 1) {
        int v = __shfl_up_sync(0xffffffffu, incl, off);
        if (lane >= off) incl += v;
    }
    if (lane == 31) wsum[wrp] = incl;
    __syncthreads();
    if (wrp == 0) {
        int s = (lane < 8) ? wsum[lane] : 0;
        #pragma unroll
        for (int off = 1; off < 8; off <<= 1) {
            int v = __shfl_up_sync(0xffffffffu, s, off);
            if (lane >= off) s += v;
        }
        if (lane < 8) wsum[lane] = s;
    }
    __syncthreads();
    const int warpOff = (wrp == 0) ? 0 : wsum[wrp - 1];
    if (tid < SCAN_BLOCKS) g_bsum[tid] = warpOff + incl - val;
    if (tid == 255) g_rowstart[NNODES] = wsum[7];
}

__global__ void __launch_bounds__(256)
k_scan_add() {
    const int i = blockIdx.x * 256 + threadIdx.x;
    if (i < NNODES) {
        const int rs = g_exloc[i] + g_bsum[blockIdx.x];
        g_rowstart[i] = rs;
        g_cursor[i] = rs;
        g_deg[i] = 0;
    }
}

__global__ void k_fill(const int4* __restrict__ edges2, int Epairs) {
    int i = blockIdx.x * blockDim.x + threadIdx.x;
    if (i < Epairs) {
        int4 e2 = edges2[i];
        int p0 = atomicAdd(&g_cursor[e2.y], 1);
        g_csr[p0] = e2.x;
        int p1 = atomicAdd(&g_cursor[e2.w], 1);
        g_csr[p1] = e2.z;
    }
}

// ---------------------------------------------------------------------------
// Packed f32x2 helpers (FFMA2 path — ptxas won't auto-fuse)
__device__ __forceinline__ unsigned long long pack2(float x, float y) {
    unsigned long long r;
    asm("mov.b64 %0, {%1, %2};" : "=l"(r) : "f"(x), "f"(y));
    return r;
}
__device__ __forceinline__ void unpack2(unsigned long long v, float& x, float& y) {
    asm("mov.b64 {%0, %1}, %2;" : "=f"(x), "=f"(y) : "l"(v));
}
__device__ __forceinline__ void fma2(unsigned long long& d,
                                     unsigned long long a,
                                     unsigned long long b) {
    asm("fma.rn.f32x2 %0, %1, %2, %0;" : "+l"(d) : "l"(a), "l"(b));
}

// ---------------------------------------------------------------------------
// Fused: aggregate 32 nodes x BOTH batches into smem (batch-packed float2),
// then GEMM(64x128x128)+bias+relu with batch-packed FFMA2 accumulators.
// GEMM inner loop processes k in pairs: A fetched as one broadcast LDS.128
// (two packed multipliers), W as LDS.128 per k. 6 smem phases/k vs FFMA2
// floor 8 pipe-cyc/k -> FFMA2-pipe-bound.
__global__ void __launch_bounds__(256, 3)
k_fused(const float* __restrict__ nodes,
        const float* __restrict__ weight,
        const float* __restrict__ bias,
        float* __restrict__ out) {
    __shared__ float2 As2[NODES_PB][FDIM];   // 32KB {batch0, batch1}
    __shared__ float Ws[32][FDIM];           // 16KB (one k-quarter of W)

    const int tid = threadIdx.x;
    const int w = tid >> 5;
    const int lane = tid & 31;
    const int node0 = blockIdx.x * NODES_PB;

    // ---- phase 1: aggregation (both batches), 8 LDGs in flight ----
    #pragma unroll 1
    for (int j = 0; j < 4; j++) {
        const int nl = w * 4 + j;            // local node 0..31
        const int n = node0 + nl;
        float4 acc0 = make_float4(0.f, 0.f, 0.f, 0.f);
        float4 acc1 = make_float4(0.f, 0.f, 0.f, 0.f);
        float scale = 0.0f;
        if (n < NNODES) {
            const int rs = g_rowstart[n];
            const int re = g_rowstart[n + 1];
            const float* nb0 = nodes + lane * 4;
            const float* nb1 = nodes + (size_t)NNODES * FDIM + lane * 4;
            int i = rs;
            for (; i + 4 <= re; i += 4) {            // MLP = 8
                int s0 = g_csr[i],     s1 = g_csr[i + 1];
                int s2 = g_csr[i + 2], s3 = g_csr[i + 3];
                float4 a0 = *(const float4*)(nb0 + (size_t)s0 * FDIM);
                float4 a1 = *(const float4*)(nb0 + (size_t)s1 * FDIM);
                float4 a2 = *(const float4*)(nb0 + (size_t)s2 * FDIM);
                float4 a3 = *(const float4*)(nb0 + (size_t)s3 * FDIM);
                float4 c0 = *(const float4*)(nb1 + (size_t)s0 * FDIM);
                float4 c1 = *(const float4*)(nb1 + (size_t)s1 * FDIM);
                float4 c2 = *(const float4*)(nb1 + (size_t)s2 * FDIM);
                float4 c3 = *(const float4*)(nb1 + (size_t)s3 * FDIM);
                acc0.x += (a0.x + a1.x) + (a2.x + a3.x);
                acc0.y += (a0.y + a1.y) + (a2.y + a3.y);
                acc0.z += (a0.z + a1.z) + (a2.z + a3.z);
                acc0.w += (a0.w + a1.w) + (a2.w + a3.w);
                acc1.x += (c0.x + c1.x) + (c2.x + c3.x);
                acc1.y += (c0.y + c1.y) + (c2.y + c3.y);
                acc1.z += (c0.z + c1.z) + (c2.z + c3.z);
                acc1.w += (c0.w + c1.w) + (c2.w + c3.w);
            }
            for (; i < re; i++) {
                int s0 = g_csr[i];
                float4 a = *(const float4*)(nb0 + (size_t)s0 * FDIM);
                float4 c = *(const float4*)(nb1 + (size_t)s0 * FDIM);
                acc0.x += a.x; acc0.y += a.y; acc0.z += a.z; acc0.w += a.w;
                acc1.x += c.x; acc1.y += c.y; acc1.z += c.z; acc1.w += c.w;
            }
            scale = 1.0f / (float)(re - rs + 1);
        }
        float4 lo = make_float4(acc0.x * scale, acc1.x * scale,
                                acc0.y * scale, acc1.y * scale);
        float4 hi = make_float4(acc0.z * scale, acc1.z * scale,
                                acc0.w * scale, acc1.w * scale);
        *(float4*)&As2[nl][lane * 4] = lo;
        *(float4*)&As2[nl][lane * 4 + 2] = hi;
    }

    // ---- phase 2: GEMM ----
    const int colg = tid & 31;    // cols 4*colg .. +4
    const int nodeg = tid >> 5;   // local nodes 4*nodeg .. +4

    const float4 b4 = *(const float4*)(bias + colg * 4);
    unsigned long long acc[4][4];   // [node][col], packed {b0,b1}
    #pragma unroll
    for (int j = 0; j < 4; j++) {
        acc[j][0] = pack2(b4.x, b4.x);
        acc[j][1] = pack2(b4.y, b4.y);
        acc[j][2] = pack2(b4.z, b4.z);
        acc[j][3] = pack2(b4.w, b4.w);
    }

    const float4* w4g = (const float4*)weight;
    #pragma unroll
    for (int kq = 0; kq < 4; kq++) {
        __syncthreads();   // kq=0: As2 ready; kq>0: prior Ws reads done
        #pragma unroll
        for (int i = 0; i < 4; i++)
            ((float4*)Ws)[tid + i * 256] = w4g[kq * 1024 + tid + i * 256];
        __syncthreads();

        #pragma unroll 4
        for (int k2 = 0; k2 < 16; k2++) {
            // A: one LDS.128 broadcast = packed multipliers for k and k+1
            ulonglong2 ap[4];
            #pragma unroll
            for (int j = 0; j < 4; j++)
                ap[j] = *(const ulonglong2*)&As2[nodeg * 4 + j][kq * 32 + k2 * 2];

            #pragma unroll
            for (int kk = 0; kk < 2; kk++) {
                const float4 wv = *(const float4*)&Ws[k2 * 2 + kk][colg * 4];
                const unsigned long long w0 = pack2(wv.x, wv.x);
                const unsigned long long w1 = pack2(wv.y, wv.y);
                const unsigned long long w2 = pack2(wv.z, wv.z);
                const unsigned long long w3 = pack2(wv.w, wv.w);
                #pragma unroll
                for (int j = 0; j < 4; j++) {
                    const unsigned long long a = kk ? ap[j].y : ap[j].x;
                    fma2(acc[j][0], w0, a);
                    fma2(acc[j][1], w1, a);
                    fma2(acc[j][2], w2, a);
                    fma2(acc[j][3], w3, a);
                }
            }
        }
    }

    // ---- store with relu (unpack batch lanes) ----
    #pragma unroll
    for (int j = 0; j < 4; j++) {
        const int n = node0 + nodeg * 4 + j;
        if (n < NNODES) {
            float x0, y0, x1, y1, x2, y2, x3, y3;
            unpack2(acc[j][0], x0, y0);
            unpack2(acc[j][1], x1, y1);
            unpack2(acc[j][2], x2, y2);
            unpack2(acc[j][3], x3, y3);
            float4 o0 = make_float4(fmaxf(x0, 0.f), fmaxf(x1, 0.f),
                                    fmaxf(x2, 0.f), fmaxf(x3, 0.f));
            float4 o1 = make_float4(fmaxf(y0, 0.f), fmaxf(y1, 0.f),
                                    fmaxf(y2, 0.f), fmaxf(y3, 0.f));
            *(float4*)(out + (size_t)n * FDIM + colg * 4) = o0;
            *(float4*)(out + (size_t)(NNODES + n) * FDIM + colg * 4) = o1;
        }
    }
}

// ---------------------------------------------------------------------------
extern "C" void kernel_launch(void* const* d_in, const int* in_sizes, int n_in,
                              void* d_out, int out_size) {
    const float* nodes = (const float*)d_in[0];
    const int4* edges2 = (const int4*)d_in[1];   // int32 [E,2], 2 edges per int4
    const float* weight = (const float*)d_in[2];
    const float* bias = (const float*)d_in[3];
    float* out = (float*)d_out;

    int E = in_sizes[1] / 2;
    if (E > EDGES_MAX) E = EDGES_MAX;
    int Epairs = E / 2;   // E is even

    k_hist<<<(Epairs + 255) / 256, 256>>>(edges2, Epairs);
    k_scan_local<<<SCAN_BLOCKS, 256>>>();
    k_scan_block<<<1, 256>>>();
    k_scan_add<<<SCAN_BLOCKS, 256>>>();
    k_fill<<<(Epairs + 255) / 256, 256>>>(edges2, Epairs);
    k_fused<<<NBLOCKS, 256>>>(nodes, weight, bias, out);
}